// round 5
// baseline (speedup 1.0000x reference)
#include <cuda_runtime.h>

#define NN 22528
#define EE 360448
#define FEA 60
#define HID 512
#define BATCH 1024
#define MAH 22
#define CATW (HID + FEA)      // 572
#define FLATK (MAH * CATW)    // 12584
#define OUTC 4
#define SLOPE 0.01f

// ---------------- scratch (device globals; no allocation allowed) -------------
__device__ int   g_is64;
__device__ float g_deg[NN];
__device__ float g_dis[NN];
__device__ int   g_cnt[NN];
__device__ int   g_off[NN + 1];
__device__ int   g_cur[NN];
__device__ int   g_row[EE];
__device__ int   g_col[EE];
__device__ int   g_srow[EE];
__device__ float g_snorm[EE];
__device__ float g_aggx[(size_t)NN * FEA];
__device__ float g_h1[(size_t)NN * HID];     // conv1 out, then conv2 out (h2)
__device__ float g_aggh[(size_t)NN * HID];
__device__ float g_cat[(size_t)NN * CATW];
__device__ float g_m0[BATCH * HID];
__device__ float g_m1[BATCH * HID];
__device__ float g_m2[BATCH * HID];

// ---------------- edge-index dtype detection ---------------------------------
__global__ void k_detect(const long long* ei) {
    int bad = 0;
    for (int i = 0; i < 256; i++) {
        long long v = ei[i];
        if (v < 0 || v >= NN) bad = 1;
    }
    g_is64 = bad ? 0 : 1;
}

__global__ void k_init_nodes() {
    int i = blockIdx.x * blockDim.x + threadIdx.x;
    if (i < NN) { g_deg[i] = 1.0f; g_cnt[i] = 0; }
}

// convert edge index + accumulate degree + histogram of col
__global__ void k_edge_accum(const void* ei, const float* __restrict__ ew) {
    int e = blockIdx.x * blockDim.x + threadIdx.x;
    if (e >= EE) return;
    int r, c;
    if (g_is64) {
        const long long* p = (const long long*)ei;
        r = (int)p[e]; c = (int)p[EE + e];
    } else {
        const int* p = (const int*)ei;
        r = p[e]; c = p[EE + e];
    }
    g_row[e] = r; g_col[e] = c;
    atomicAdd(&g_deg[c], ew[e]);
    atomicAdd(&g_cnt[c], 1);
}

__global__ void k_dis() {
    int i = blockIdx.x * blockDim.x + threadIdx.x;
    if (i < NN) g_dis[i] = rsqrtf(g_deg[i]);   // deg >= 1 (self loop)
}

// exclusive scan of g_cnt -> g_off / g_cur. NN = 1024 * 22 exactly.
__global__ void k_scan() {
    __shared__ int sums[1024];
    const int CH = NN / 1024;   // 22
    int t = threadIdx.x;
    int base = t * CH;
    int loc[CH];
    int s = 0;
#pragma unroll
    for (int i = 0; i < CH; i++) { loc[i] = s; s += g_cnt[base + i]; }
    sums[t] = s;
    __syncthreads();
    for (int d = 1; d < 1024; d <<= 1) {
        int v = 0;
        if (t >= d) v = sums[t - d];
        __syncthreads();
        if (t >= d) sums[t] += v;
        __syncthreads();
    }
    int off = (t == 0) ? 0 : sums[t - 1];
#pragma unroll
    for (int i = 0; i < CH; i++) {
        int o = off + loc[i];
        g_off[base + i] = o;
        g_cur[base + i] = o;
    }
    if (t == 1023) g_off[NN] = sums[1023];
}

__global__ void k_fill(const float* __restrict__ ew) {
    int e = blockIdx.x * blockDim.x + threadIdx.x;
    if (e >= EE) return;
    int r = g_row[e], c = g_col[e];
    int p = atomicAdd(&g_cur[c], 1);
    g_srow[p] = r;
    g_snorm[p] = g_dis[r] * ew[e] * g_dis[c];
}

// ---------------- graph aggregation (gather, CSR) -----------------------------
// width 60 (raw features): one block per node, 64 threads
__global__ void k_gather_fea(const float* __restrict__ x) {
    int n = blockIdx.x;
    int t = threadIdx.x;
    __shared__ int   sr[64];
    __shared__ float sw[64];
    int beg = g_off[n], end = g_off[n + 1];
    float dn = g_dis[n];
    float self = dn * dn;
    float acc = 0.f;
    if (t < FEA) acc = x[(size_t)n * FEA + t] * self;
    for (int ch = beg; ch < end; ch += 64) {
        int m = min(64, end - ch);
        if (t < m) { sr[t] = g_srow[ch + t]; sw[t] = g_snorm[ch + t]; }
        __syncthreads();
        if (t < FEA) {
            for (int k = 0; k < m; k++)
                acc = fmaf(x[(size_t)sr[k] * FEA + t], sw[k], acc);
        }
        __syncthreads();
    }
    if (t < FEA) g_aggx[(size_t)n * FEA + t] = acc;
}

// width 512: one block per node, 128 threads, float4 per thread
__global__ void k_gather_hid(const float* __restrict__ in, float* __restrict__ out) {
    int n = blockIdx.x;
    int t = threadIdx.x;
    __shared__ int   sr[64];
    __shared__ float sw[64];
    int beg = g_off[n], end = g_off[n + 1];
    float dn = g_dis[n];
    float self = dn * dn;
    float4 acc = *(const float4*)(in + (size_t)n * HID + t * 4);
    acc.x *= self; acc.y *= self; acc.z *= self; acc.w *= self;
    for (int ch = beg; ch < end; ch += 64) {
        int m = min(64, end - ch);
        if (t < m) { sr[t] = g_srow[ch + t]; sw[t] = g_snorm[ch + t]; }
        __syncthreads();
        for (int k = 0; k < m; k++) {
            float4 u = *(const float4*)(in + (size_t)sr[k] * HID + t * 4);
            float w = sw[k];
            acc.x = fmaf(u.x, w, acc.x);
            acc.y = fmaf(u.y, w, acc.y);
            acc.z = fmaf(u.z, w, acc.z);
            acc.w = fmaf(u.w, w, acc.w);
        }
        __syncthreads();
    }
    *(float4*)(out + (size_t)n * HID + t * 4) = acc;
}

// ---------------- fp32 register-blocked GEMM ----------------------------------
// C[M,Nn] = A[M,K] @ W[K,Nn] (+ bias, lrelu) ; optional split-K (atomic accumulate)
// BM=128, BN=64, BK=16, TM=8, TN=4, 256 threads. M%128==0, Nn%64==0 assumed.
template <bool ATOMIC, bool LRELU>
__global__ __launch_bounds__(256) void k_gemm(
    const float* __restrict__ A, const float* __restrict__ W,
    const float* __restrict__ bias, float* __restrict__ C,
    int M, int Nn, int K, int KS)
{
    const int BK = 16;
    __shared__ float As[16][128 + 4];
    __shared__ float Ws[16][64 + 4];
    int tid = threadIdx.x;
    int tx = tid & 15;        // N dir
    int ty = tid >> 4;        // M dir
    int rowBase = blockIdx.y * 128;
    int colBase = blockIdx.x * 64;
    int kbeg = blockIdx.z * KS;
    int kend = min(K, kbeg + KS);
    float acc[8][4] = {};

    for (int k0 = kbeg; k0 < kend; k0 += BK) {
        // load A tile: 128x16 = 2048 floats, 2 float4 per thread
#pragma unroll
        for (int l = 0; l < 2; l++) {
            int f = tid * 2 + l;
            int ar = f >> 2;
            int ac = (f & 3) * 4;
            int kk = k0 + ac;
            const float* Ap = A + (size_t)(rowBase + ar) * K + kk;
            float4 v;
            if (kk + 3 < kend) {
                v = *(const float4*)Ap;
            } else {
                v.x = (kk     < kend) ? Ap[0] : 0.f;
                v.y = (kk + 1 < kend) ? Ap[1] : 0.f;
                v.z = (kk + 2 < kend) ? Ap[2] : 0.f;
                v.w = (kk + 3 < kend) ? Ap[3] : 0.f;
            }
            As[ac + 0][ar] = v.x; As[ac + 1][ar] = v.y;
            As[ac + 2][ar] = v.z; As[ac + 3][ar] = v.w;
        }
        // load W tile: 16x64 floats, 1 float4 per thread
        {
            int wr = tid >> 4;
            int wc = (tid & 15) * 4;
            int kk = k0 + wr;
            float4 v = make_float4(0.f, 0.f, 0.f, 0.f);
            if (kk < kend) v = *(const float4*)(W + (size_t)kk * Nn + colBase + wc);
            *(float4*)&Ws[wr][wc] = v;
        }
        __syncthreads();
#pragma unroll
        for (int k = 0; k < BK; k++) {
            float ra[8], rb[4];
            *(float4*)&ra[0] = *(const float4*)&As[k][ty * 8];
            *(float4*)&ra[4] = *(const float4*)&As[k][ty * 8 + 4];
            *(float4*)&rb[0] = *(const float4*)&Ws[k][tx * 4];
#pragma unroll
            for (int i = 0; i < 8; i++)
#pragma unroll
                for (int j = 0; j < 4; j++)
                    acc[i][j] = fmaf(ra[i], rb[j], acc[i][j]);
        }
        __syncthreads();
    }

#pragma unroll
    for (int i = 0; i < 8; i++) {
        int r = rowBase + ty * 8 + i;
        int c0 = colBase + tx * 4;
        if (ATOMIC) {
#pragma unroll
            for (int j = 0; j < 4; j++)
                atomicAdd(&C[(size_t)r * Nn + c0 + j], acc[i][j]);
        } else {
            float4 v;
            v.x = acc[i][0] + bias[c0 + 0];
            v.y = acc[i][1] + bias[c0 + 1];
            v.z = acc[i][2] + bias[c0 + 2];
            v.w = acc[i][3] + bias[c0 + 3];
            if (LRELU) {
                v.x = v.x > 0.f ? v.x : SLOPE * v.x;
                v.y = v.y > 0.f ? v.y : SLOPE * v.y;
                v.z = v.z > 0.f ? v.z : SLOPE * v.z;
                v.w = v.w > 0.f ? v.w : SLOPE * v.w;
            }
            *(float4*)&C[(size_t)r * Nn + c0] = v;
        }
    }
}

// ---------------- misc elementwise --------------------------------------------
__global__ void k_concat(const float* __restrict__ x) {
    int i = blockIdx.x * blockDim.x + threadIdx.x;
    if (i >= NN * CATW) return;
    int node = i / CATW;
    int c = i - node * CATW;
    g_cat[i] = (c < HID) ? g_h1[(size_t)node * HID + c]
                         : x[(size_t)node * FEA + (c - HID)];
}

__global__ void k_init_bias(float* __restrict__ C, const float* __restrict__ b, int Nn, int total) {
    int i = blockIdx.x * blockDim.x + threadIdx.x;
    if (i < total) C[i] = b[i % Nn];
}

__global__ void k_lrelu(float* __restrict__ C, int total) {
    int i = blockIdx.x * blockDim.x + threadIdx.x;
    if (i < total) {
        float v = C[i];
        C[i] = v > 0.f ? v : SLOPE * v;
    }
}

// ---------------- final layer + log_softmax -----------------------------------
__global__ void k_logits(const float* __restrict__ m2, const float* __restrict__ Wo,
                         const float* __restrict__ bo, float* __restrict__ out) {
    int b = blockIdx.x;          // 1024
    int t = threadIdx.x;         // 128
    int w = t >> 5, lane = t & 31;
    float s = 0.f;
    const float* mr = m2 + (size_t)b * HID;
    for (int k = lane; k < HID; k += 32)
        s = fmaf(mr[k], Wo[k * OUTC + w], s);
#pragma unroll
    for (int o = 16; o; o >>= 1) s += __shfl_xor_sync(0xffffffffu, s, o);
    __shared__ float lg[OUTC];
    if (lane == 0) lg[w] = s + bo[w];
    __syncthreads();
    if (t == 0) {
        float a = lg[0], bb = lg[1], c = lg[2], d = lg[3];
        float mx = fmaxf(fmaxf(a, bb), fmaxf(c, d));
        float se = expf(a - mx) + expf(bb - mx) + expf(c - mx) + expf(d - mx);
        float l = mx + logf(se);
        out[b * OUTC + 0] = a - l;
        out[b * OUTC + 1] = bb - l;
        out[b * OUTC + 2] = c - l;
        out[b * OUTC + 3] = d - l;
    }
}

// ---------------- launch -------------------------------------------------------
extern "C" void kernel_launch(void* const* d_in, const int* in_sizes, int n_in,
                              void* d_out, int out_size) {
    const float* x   = (const float*)d_in[0];
    const void*  ei  = d_in[1];
    const float* ew  = (const float*)d_in[2];
    const float* W1  = (const float*)d_in[3];
    const float* b1  = (const float*)d_in[4];
    const float* W2  = (const float*)d_in[5];
    const float* b2  = (const float*)d_in[6];
    const float* Wf0 = (const float*)d_in[7];
    const float* bf0 = (const float*)d_in[8];
    const float* Wf1 = (const float*)d_in[9];
    const float* bf1 = (const float*)d_in[10];
    const float* Wf2 = (const float*)d_in[11];
    const float* bf2 = (const float*)d_in[12];
    const float* Wo  = (const float*)d_in[13];
    const float* bo  = (const float*)d_in[14];
    float* out = (float*)d_out;

    float *aggx, *h1, *aggh, *cat, *m0, *m1, *m2;
    cudaGetSymbolAddress((void**)&aggx, g_aggx);
    cudaGetSymbolAddress((void**)&h1,   g_h1);
    cudaGetSymbolAddress((void**)&aggh, g_aggh);
    cudaGetSymbolAddress((void**)&cat,  g_cat);
    cudaGetSymbolAddress((void**)&m0,   g_m0);
    cudaGetSymbolAddress((void**)&m1,   g_m1);
    cudaGetSymbolAddress((void**)&m2,   g_m2);

    // ---- graph normalization + CSR build ----
    k_detect<<<1, 1>>>((const long long*)ei);
    k_init_nodes<<<(NN + 255) / 256, 256>>>();
    k_edge_accum<<<(EE + 255) / 256, 256>>>(ei, ew);
    k_dis<<<(NN + 255) / 256, 256>>>();
    k_scan<<<1, 1024>>>();
    k_fill<<<(EE + 255) / 256, 256>>>(ew);

    // ---- conv1: aggregate(x) then GEMM ----
    k_gather_fea<<<NN, 64>>>(x);
    k_gemm<false, true><<<dim3(HID / 64, NN / 128, 1), 256>>>(aggx, W1, b1, h1, NN, HID, FEA, FEA);

    // ---- conv2: aggregate(h1) then GEMM (writes h2 into h1 buffer) ----
    k_gather_hid<<<NN, 128>>>(h1, aggh);
    k_gemm<false, true><<<dim3(HID / 64, NN / 128, 1), 256>>>(aggh, W2, b2, h1, NN, HID, HID, HID);

    // ---- concat [h2, x] -> [1024, 12584] (node-major == flat layout) ----
    k_concat<<<(NN * CATW + 255) / 256, 256>>>(x);

    // ---- MLP layer 0 (split-K x8 + atomic accumulate) ----
    k_init_bias<<<(BATCH * HID + 255) / 256, 256>>>(m0, bf0, HID, BATCH * HID);
    k_gemm<true, false><<<dim3(HID / 64, BATCH / 128, 8), 256>>>(cat, Wf0, nullptr, m0, BATCH, HID, FLATK, 1576);
    k_lrelu<<<(BATCH * HID + 255) / 256, 256>>>(m0, BATCH * HID);

    // ---- MLP layer 1 ----
    k_init_bias<<<(BATCH * HID + 255) / 256, 256>>>(m1, bf1, HID, BATCH * HID);
    k_gemm<true, false><<<dim3(HID / 64, BATCH / 128, 4), 256>>>(m0, Wf1, nullptr, m1, BATCH, HID, HID, 128);
    k_lrelu<<<(BATCH * HID + 255) / 256, 256>>>(m1, BATCH * HID);

    // ---- MLP layer 2 ----
    k_init_bias<<<(BATCH * HID + 255) / 256, 256>>>(m2, bf2, HID, BATCH * HID);
    k_gemm<true, false><<<dim3(HID / 64, BATCH / 128, 4), 256>>>(m1, Wf2, nullptr, m2, BATCH, HID, HID, 128);
    k_lrelu<<<(BATCH * HID + 255) / 256, 256>>>(m2, BATCH * HID);

    // ---- output head + log_softmax ----
    k_logits<<<BATCH, 128>>>(m2, Wo, bo, out);
}

// round 15
// speedup vs baseline: 1.8522x; 1.8522x over previous
#include <cuda_runtime.h>
#include <cuda_bf16.h>
#include <cstdint>

#define NN 22528
#define EE 360448
#define FEA 60
#define HID 512
#define BATCH 1024
#define CATW 572          // HID + FEA
#define FLATK 12584       // 22 * CATW
#define FLATKP 12608      // padded to %32
#define OUTC 4
#define SLOPE 0.01f

// ---- mma.sync GEMM tile config ----
#define BM 128
#define BN 64
#define BK 32
#define ASTRIDE 80        // smem row stride bytes (32 bf16 = 64B data + 16B pad)
#define SM_AH 0
#define SM_AL 10240
#define SM_BH 20480
#define SM_BL 25600
#define STAGE_BYTES 30720
#define SMEM_T (2 * STAGE_BYTES)   // 61440

// ---------------- scratch (device globals; no allocation allowed) -------------
__device__ int   g_is64;
__device__ float g_deg[NN];
__device__ float g_dis[NN];
__device__ int   g_cnt[NN];
__device__ int   g_off[NN + 1];
__device__ int   g_cur[NN];
__device__ int   g_row[EE];
__device__ int   g_col[EE];
__device__ int   g_srow[EE];
__device__ float g_snorm[EE];
__device__ float g_h1[(size_t)NN * HID];          // conv1 out, then conv2 out
__device__ float g_m0[BATCH * HID];
__device__ float g_m2[BATCH * HID];
// bf16 hi/lo activations
__device__ __nv_bfloat16 g_axh[(size_t)NN * 64],  g_axl[(size_t)NN * 64];
__device__ __nv_bfloat16 g_ahh[(size_t)NN * HID], g_ahl[(size_t)NN * HID];
__device__ __nv_bfloat16 g_cth[(size_t)BATCH * FLATKP], g_ctl[(size_t)BATCH * FLATKP];
__device__ __nv_bfloat16 g_m0h[BATCH * HID], g_m0l[BATCH * HID];
__device__ __nv_bfloat16 g_m1h[BATCH * HID], g_m1l[BATCH * HID];
// transposed + split weights: [Nn][KP] row-major
__device__ __nv_bfloat16 g_wt1h[(size_t)HID * 64],     g_wt1l[(size_t)HID * 64];
__device__ __nv_bfloat16 g_wt2h[(size_t)HID * HID],    g_wt2l[(size_t)HID * HID];
__device__ __nv_bfloat16 g_wf0h[(size_t)HID * FLATKP], g_wf0l[(size_t)HID * FLATKP];
__device__ __nv_bfloat16 g_wf1h[(size_t)HID * HID],    g_wf1l[(size_t)HID * HID];
__device__ __nv_bfloat16 g_wf2h[(size_t)HID * HID],    g_wf2l[(size_t)HID * HID];

// ---------------- helpers ------------------------------------------------------
__device__ __forceinline__ void split2(float v, __nv_bfloat16& h, __nv_bfloat16& l) {
    h = __float2bfloat16(v);
    l = __float2bfloat16(v - __bfloat162float(h));
}
__device__ __forceinline__ uint32_t smem_u32(const void* p) {
    uint32_t a;
    asm("{ .reg .u64 t; cvta.to.shared.u64 t, %1; cvt.u32.u64 %0, t; }" : "=r"(a) : "l"(p));
    return a;
}
__device__ __forceinline__ void cpa16(uint32_t dst, const void* src) {
    asm volatile("cp.async.cg.shared.global [%0], [%1], 16;" :: "r"(dst), "l"(src));
}
__device__ __forceinline__ void ldmx4(uint32_t* r, uint32_t addr) {
    asm volatile("ldmatrix.sync.aligned.m8n8.x4.shared.b16 {%0,%1,%2,%3}, [%4];"
        : "=r"(r[0]), "=r"(r[1]), "=r"(r[2]), "=r"(r[3]) : "r"(addr));
}
__device__ __forceinline__ void ldmx2(uint32_t* r, uint32_t addr) {
    asm volatile("ldmatrix.sync.aligned.m8n8.x2.shared.b16 {%0,%1}, [%2];"
        : "=r"(r[0]), "=r"(r[1]) : "r"(addr));
}
__device__ __forceinline__ void mma16816(float* c, const uint32_t* a, const uint32_t* b) {
    asm volatile("mma.sync.aligned.m16n8k16.row.col.f32.bf16.bf16.f32 "
        "{%0,%1,%2,%3}, {%4,%5,%6,%7}, {%8,%9}, {%0,%1,%2,%3};"
        : "+f"(c[0]), "+f"(c[1]), "+f"(c[2]), "+f"(c[3])
        : "r"(a[0]), "r"(a[1]), "r"(a[2]), "r"(a[3]), "r"(b[0]), "r"(b[1]));
}

// ---------------- edge-index dtype detection ---------------------------------
__global__ void k_detect(const long long* ei) {
    int bad = 0;
    for (int i = 0; i < 256; i++) {
        long long v = ei[i];
        if (v < 0 || v >= NN) bad = 1;
    }
    g_is64 = bad ? 0 : 1;
}

__global__ void k_init_nodes() {
    int i = blockIdx.x * blockDim.x + threadIdx.x;
    if (i < NN) { g_deg[i] = 1.0f; g_cnt[i] = 0; }
}

__global__ void k_edge_accum(const void* ei, const float* __restrict__ ew) {
    int e = blockIdx.x * blockDim.x + threadIdx.x;
    if (e >= EE) return;
    int r, c;
    if (g_is64) {
        const long long* p = (const long long*)ei;
        r = (int)p[e]; c = (int)p[EE + e];
    } else {
        const int* p = (const int*)ei;
        r = p[e]; c = p[EE + e];
    }
    g_row[e] = r; g_col[e] = c;
    atomicAdd(&g_deg[c], ew[e]);
    atomicAdd(&g_cnt[c], 1);
}

__global__ void k_dis() {
    int i = blockIdx.x * blockDim.x + threadIdx.x;
    if (i < NN) g_dis[i] = rsqrtf(g_deg[i]);
}

__global__ void k_scan() {
    __shared__ int sums[1024];
    const int CH = NN / 1024;   // 22
    int t = threadIdx.x;
    int base = t * CH;
    int loc[CH];
    int s = 0;
#pragma unroll
    for (int i = 0; i < CH; i++) { loc[i] = s; s += g_cnt[base + i]; }
    sums[t] = s;
    __syncthreads();
    for (int d = 1; d < 1024; d <<= 1) {
        int v = 0;
        if (t >= d) v = sums[t - d];
        __syncthreads();
        if (t >= d) sums[t] += v;
        __syncthreads();
    }
    int off = (t == 0) ? 0 : sums[t - 1];
#pragma unroll
    for (int i = 0; i < CH; i++) {
        int o = off + loc[i];
        g_off[base + i] = o;
        g_cur[base + i] = o;
    }
    if (t == 1023) g_off[NN] = sums[1023];
}

__global__ void k_fill(const float* __restrict__ ew) {
    int e = blockIdx.x * blockDim.x + threadIdx.x;
    if (e >= EE) return;
    int r = g_row[e], c = g_col[e];
    int p = atomicAdd(&g_cur[c], 1);
    g_srow[p] = r;
    g_snorm[p] = g_dis[r] * ew[e] * g_dis[c];
}

// ---------------- graph aggregation (gather, CSR) → bf16 split ----------------
__global__ void k_gather_fea(const float* __restrict__ x) {
    int n = blockIdx.x;
    int t = threadIdx.x;   // 64
    __shared__ int   sr[64];
    __shared__ float sw[64];
    int beg = g_off[n], end = g_off[n + 1];
    float dn = g_dis[n];
    float self = dn * dn;
    float acc = 0.f;
    if (t < FEA) acc = x[(size_t)n * FEA + t] * self;
    for (int ch = beg; ch < end; ch += 64) {
        int m = min(64, end - ch);
        if (t < m) { sr[t] = g_srow[ch + t]; sw[t] = g_snorm[ch + t]; }
        __syncthreads();
        if (t < FEA) {
            for (int k = 0; k < m; k++)
                acc = fmaf(x[(size_t)sr[k] * FEA + t], sw[k], acc);
        }
        __syncthreads();
    }
    float v = (t < FEA) ? acc : 0.f;
    __nv_bfloat16 h, l;
    split2(v, h, l);
    g_axh[(size_t)n * 64 + t] = h;
    g_axl[(size_t)n * 64 + t] = l;
}

__global__ void k_gather_hid(const float* __restrict__ in) {
    int n = blockIdx.x;
    int t = threadIdx.x;   // 128
    __shared__ int   sr[64];
    __shared__ float sw[64];
    int beg = g_off[n], end = g_off[n + 1];
    float dn = g_dis[n];
    float self = dn * dn;
    float4 acc = *(const float4*)(in + (size_t)n * HID + t * 4);
    acc.x *= self; acc.y *= self; acc.z *= self; acc.w *= self;
    for (int ch = beg; ch < end; ch += 64) {
        int m = min(64, end - ch);
        if (t < m) { sr[t] = g_srow[ch + t]; sw[t] = g_snorm[ch + t]; }
        __syncthreads();
        for (int k = 0; k < m; k++) {
            float4 u = *(const float4*)(in + (size_t)sr[k] * HID + t * 4);
            float w = sw[k];
            acc.x = fmaf(u.x, w, acc.x);
            acc.y = fmaf(u.y, w, acc.y);
            acc.z = fmaf(u.z, w, acc.z);
            acc.w = fmaf(u.w, w, acc.w);
        }
        __syncthreads();
    }
    __nv_bfloat16 h0, l0, h1, l1, h2, l2, h3, l3;
    split2(acc.x, h0, l0); split2(acc.y, h1, l1);
    split2(acc.z, h2, l2); split2(acc.w, h3, l3);
    size_t o = (size_t)n * HID + t * 4;
    g_ahh[o + 0] = h0; g_ahh[o + 1] = h1; g_ahh[o + 2] = h2; g_ahh[o + 3] = h3;
    g_ahl[o + 0] = l0; g_ahl[o + 1] = l1; g_ahl[o + 2] = l2; g_ahl[o + 3] = l3;
}

// ---------------- weight transpose + split: W[K][Nn] -> Wh/Wl[Nn][KP] ---------
__global__ void k_wt(const float* __restrict__ W, __nv_bfloat16* __restrict__ Wh,
                     __nv_bfloat16* __restrict__ Wl, int K, int KP, int Nn) {
    __shared__ float sm[32][33];
    int k0 = blockIdx.x * 32, n0 = blockIdx.y * 32;
    int tx = threadIdx.x, ty = threadIdx.y;   // (32, 8)
    for (int i = ty; i < 32; i += 8) {
        int k = k0 + i;
        sm[i][tx] = (k < K) ? W[(size_t)k * Nn + n0 + tx] : 0.f;
    }
    __syncthreads();
    for (int i = ty; i < 32; i += 8) {
        int n = n0 + i, k = k0 + tx;
        float v = sm[tx][i];
        __nv_bfloat16 h, l;
        split2(v, h, l);
        Wh[(size_t)n * KP + k] = h;
        Wl[(size_t)n * KP + k] = l;
    }
}

// ---------------- bf16 mma.sync GEMM -------------------------------------------
// C[M,Nn] = A @ B^T, A=[M][K] hi/lo bf16, B=[Nn][K] hi/lo bf16 (K contiguous)
// 3-term split accumulated in fp32. EPI: 0=bias+lrelu->f32, 1=atomicAdd->f32,
// 2=bias+lrelu->bf16 hi/lo pair. grid (Nn/64, M/128, Z); chunksPerSlab = split-K.
template <int EPI>
__global__ __launch_bounds__(256) void tgemm(
    const __nv_bfloat16* __restrict__ Ah, const __nv_bfloat16* __restrict__ Al,
    const __nv_bfloat16* __restrict__ Bh, const __nv_bfloat16* __restrict__ Bl,
    const float* __restrict__ bias, float* __restrict__ C,
    __nv_bfloat16* __restrict__ Ch, __nv_bfloat16* __restrict__ Cl,
    int Nn, int K, int chunksPerSlab)
{
    extern __shared__ char smem[];
    uint32_t sbase = smem_u32(smem);
    int tid = threadIdx.x, lane = tid & 31, w = tid >> 5;
    int wm = w & 3, wn = w >> 2;              // 4 x 2 warps, warp tile 32x32
    int rowBase = blockIdx.y * BM, colBase = blockIdx.x * BN;
    int total = K / BK;
    int c0 = blockIdx.z * chunksPerSlab;
    int c1 = min(total, c0 + chunksPerSlab);

    float acc[2][4][4];
#pragma unroll
    for (int i = 0; i < 2; i++)
#pragma unroll
        for (int j = 0; j < 4; j++)
#pragma unroll
            for (int q = 0; q < 4; q++) acc[i][j][q] = 0.f;

#define LOADSTAGE(chunk, stg) do {                                             \
        int kk = (chunk) * BK;                                                 \
        uint32_t sb = sbase + (stg) * STAGE_BYTES;                             \
        _Pragma("unroll")                                                      \
        for (int i_ = 0; i_ < 2; i_++) {                                       \
            int t2 = tid + i_ * 256; int r_ = t2 >> 2, c_ = t2 & 3;            \
            size_t so = (size_t)(rowBase + r_) * K + kk + c_ * 8;              \
            uint32_t d_ = sb + r_ * ASTRIDE + c_ * 16;                         \
            cpa16(d_ + SM_AH, Ah + so);                                        \
            cpa16(d_ + SM_AL, Al + so);                                        \
        }                                                                      \
        {                                                                      \
            int r_ = tid >> 2, c_ = tid & 3;                                   \
            size_t so = (size_t)(colBase + r_) * K + kk + c_ * 8;              \
            uint32_t d_ = sb + r_ * ASTRIDE + c_ * 16;                         \
            cpa16(d_ + SM_BH, Bh + so);                                        \
            cpa16(d_ + SM_BL, Bl + so);                                        \
        }                                                                      \
        asm volatile("cp.async.commit_group;" ::: "memory");                   \
    } while (0)

    LOADSTAGE(c0, 0);
    for (int c = c0; c < c1; ++c) {
        int stg = (c - c0) & 1;
        if (c + 1 < c1) {
            LOADSTAGE(c + 1, stg ^ 1);
            asm volatile("cp.async.wait_group 1;" ::: "memory");
        } else {
            asm volatile("cp.async.wait_group 0;" ::: "memory");
        }
        __syncthreads();
        uint32_t sb = sbase + stg * STAGE_BYTES;
        uint32_t aB = sb + SM_AH + wm * 32 * ASTRIDE;
        uint32_t bB = sb + SM_BH + wn * 32 * ASTRIDE;
        int lr = lane & 15, lh = lane >> 4;
        int bn = lane & 7, bk = (lane >> 3) & 1;
#pragma unroll
        for (int ks = 0; ks < 2; ks++) {
            int ko = ks * 32;   // bytes (16 bf16)
            uint32_t ah[2][4], al[2][4], bh[4][2], bl[4][2];
#pragma unroll
            for (int mi = 0; mi < 2; mi++) {
                uint32_t ad = aB + (mi * 16 + lr) * ASTRIDE + ko + lh * 16;
                ldmx4(ah[mi], ad);
                ldmx4(al[mi], ad + (SM_AL - SM_AH));
            }
#pragma unroll
            for (int ni = 0; ni < 4; ni++) {
                uint32_t bd = bB + (ni * 8 + bn) * ASTRIDE + ko + bk * 16;
                ldmx2(bh[ni], bd);
                ldmx2(bl[ni], bd + (SM_BL - SM_BH));
            }
#pragma unroll
            for (int mi = 0; mi < 2; mi++)
#pragma unroll
                for (int ni = 0; ni < 4; ni++) {
                    mma16816(acc[mi][ni], ah[mi], bh[ni]);
                    mma16816(acc[mi][ni], al[mi], bh[ni]);
                    mma16816(acc[mi][ni], ah[mi], bl[ni]);
                }
        }
        __syncthreads();
    }
#undef LOADSTAGE

    // epilogue
    int r0 = rowBase + wm * 32 + (lane >> 2);
    int cB = colBase + wn * 32 + 2 * (lane & 3);
#pragma unroll
    for (int mi = 0; mi < 2; mi++)
#pragma unroll
        for (int ni = 0; ni < 4; ni++) {
            int row = r0 + mi * 16, col = cB + ni * 8;
            float* a = acc[mi][ni];
            if (EPI == 1) {
                atomicAdd(&C[(size_t)row * Nn + col],           a[0]);
                atomicAdd(&C[(size_t)row * Nn + col + 1],       a[1]);
                atomicAdd(&C[(size_t)(row + 8) * Nn + col],     a[2]);
                atomicAdd(&C[(size_t)(row + 8) * Nn + col + 1], a[3]);
            } else {
                float b0 = bias[col], b1 = bias[col + 1];
                float v0 = a[0] + b0, v1 = a[1] + b1;
                float v2 = a[2] + b0, v3 = a[3] + b1;
                v0 = v0 > 0.f ? v0 : SLOPE * v0;
                v1 = v1 > 0.f ? v1 : SLOPE * v1;
                v2 = v2 > 0.f ? v2 : SLOPE * v2;
                v3 = v3 > 0.f ? v3 : SLOPE * v3;
                if (EPI == 0) {
                    *(float2*)&C[(size_t)row * Nn + col]       = make_float2(v0, v1);
                    *(float2*)&C[(size_t)(row + 8) * Nn + col] = make_float2(v2, v3);
                } else {
                    __nv_bfloat16 h0, l0, h1, l1, h2, l2, h3, l3;
                    split2(v0, h0, l0); split2(v1, h1, l1);
                    split2(v2, h2, l2); split2(v3, h3, l3);
                    __nv_bfloat162 H0; H0.x = h0; H0.y = h1;
                    __nv_bfloat162 L0; L0.x = l0; L0.y = l1;
                    __nv_bfloat162 H1; H1.x = h2; H1.y = h3;
                    __nv_bfloat162 L1; L1.x = l2; L1.y = l3;
                    *(__nv_bfloat162*)&Ch[(size_t)row * Nn + col]       = H0;
                    *(__nv_bfloat162*)&Cl[(size_t)row * Nn + col]       = L0;
                    *(__nv_bfloat162*)&Ch[(size_t)(row + 8) * Nn + col] = H1;
                    *(__nv_bfloat162*)&Cl[(size_t)(row + 8) * Nn + col] = L1;
                }
            }
        }
}

// ---------------- misc elementwise --------------------------------------------
__global__ void k_concat(const float* __restrict__ x, const float* __restrict__ h1) {
    int i = blockIdx.x * blockDim.x + threadIdx.x;
    if (i >= BATCH * FLATKP) return;
    int b = i / FLATKP;
    int j = i - b * FLATKP;
    float v = 0.f;
    if (j < FLATK) {
        int node = b * 22 + j / CATW;
        int c = j % CATW;
        v = (c < HID) ? h1[(size_t)node * HID + c] : x[(size_t)node * FEA + (c - HID)];
    }
    __nv_bfloat16 h, l;
    split2(v, h, l);
    g_cth[i] = h; g_ctl[i] = l;
}

__global__ void k_init_bias(float* __restrict__ C, const float* __restrict__ b, int Nn, int total) {
    int i = blockIdx.x * blockDim.x + threadIdx.x;
    if (i < total) C[i] = b[i % Nn];
}

__global__ void k_lrelu_split(const float* __restrict__ m,
                              __nv_bfloat16* __restrict__ mh, __nv_bfloat16* __restrict__ ml,
                              int total) {
    int i = blockIdx.x * blockDim.x + threadIdx.x;
    if (i >= total) return;
    float v = m[i];
    v = v > 0.f ? v : SLOPE * v;
    __nv_bfloat16 h, l;
    split2(v, h, l);
    mh[i] = h; ml[i] = l;
}

// ---------------- final layer + log_softmax -----------------------------------
__global__ void k_logits(const float* __restrict__ m2, const float* __restrict__ Wo,
                         const float* __restrict__ bo, float* __restrict__ out) {
    int b = blockIdx.x;
    int t = threadIdx.x;
    int w = t >> 5, lane = t & 31;
    float s = 0.f;
    const float* mr = m2 + (size_t)b * HID;
    for (int k = lane; k < HID; k += 32)
        s = fmaf(mr[k], Wo[k * OUTC + w], s);
#pragma unroll
    for (int o = 16; o; o >>= 1) s += __shfl_xor_sync(0xffffffffu, s, o);
    __shared__ float lg[OUTC];
    if (lane == 0) lg[w] = s + bo[w];
    __syncthreads();
    if (t == 0) {
        float a = lg[0], bb = lg[1], c = lg[2], d = lg[3];
        float mx = fmaxf(fmaxf(a, bb), fmaxf(c, d));
        float se = expf(a - mx) + expf(bb - mx) + expf(c - mx) + expf(d - mx);
        float l = mx + logf(se);
        out[b * OUTC + 0] = a - l;
        out[b * OUTC + 1] = bb - l;
        out[b * OUTC + 2] = c - l;
        out[b * OUTC + 3] = d - l;
    }
}

// ---------------- launch -------------------------------------------------------
extern "C" void kernel_launch(void* const* d_in, const int* in_sizes, int n_in,
                              void* d_out, int out_size) {
    const float* x   = (const float*)d_in[0];
    const void*  ei  = d_in[1];
    const float* ew  = (const float*)d_in[2];
    const float* W1  = (const float*)d_in[3];
    const float* b1  = (const float*)d_in[4];
    const float* W2  = (const float*)d_in[5];
    const float* b2  = (const float*)d_in[6];
    const float* Wf0 = (const float*)d_in[7];
    const float* bf0 = (const float*)d_in[8];
    const float* Wf1 = (const float*)d_in[9];
    const float* bf1 = (const float*)d_in[10];
    const float* Wf2 = (const float*)d_in[11];
    const float* bf2 = (const float*)d_in[12];
    const float* Wo  = (const float*)d_in[13];
    const float* bo  = (const float*)d_in[14];
    float* out = (float*)d_out;

    cudaFuncSetAttribute(tgemm<0>, cudaFuncAttributeMaxDynamicSharedMemorySize, SMEM_T);
    cudaFuncSetAttribute(tgemm<1>, cudaFuncAttributeMaxDynamicSharedMemorySize, SMEM_T);
    cudaFuncSetAttribute(tgemm<2>, cudaFuncAttributeMaxDynamicSharedMemorySize, SMEM_T);

    float *h1, *m0, *m2;
    __nv_bfloat16 *axh, *axl, *ahh, *ahl, *cth, *ctl, *m0h, *m0l, *m1h, *m1l;
    __nv_bfloat16 *wt1h, *wt1l, *wt2h, *wt2l, *wf0h, *wf0l, *wf1h, *wf1l, *wf2h, *wf2l;
    cudaGetSymbolAddress((void**)&h1,  g_h1);
    cudaGetSymbolAddress((void**)&m0,  g_m0);
    cudaGetSymbolAddress((void**)&m2,  g_m2);
    cudaGetSymbolAddress((void**)&axh, g_axh);  cudaGetSymbolAddress((void**)&axl, g_axl);
    cudaGetSymbolAddress((void**)&ahh, g_ahh);  cudaGetSymbolAddress((void**)&ahl, g_ahl);
    cudaGetSymbolAddress((void**)&cth, g_cth);  cudaGetSymbolAddress((void**)&ctl, g_ctl);
    cudaGetSymbolAddress((void**)&m0h, g_m0h);  cudaGetSymbolAddress((void**)&m0l, g_m0l);
    cudaGetSymbolAddress((void**)&m1h, g_m1h);  cudaGetSymbolAddress((void**)&m1l, g_m1l);
    cudaGetSymbolAddress((void**)&wt1h, g_wt1h); cudaGetSymbolAddress((void**)&wt1l, g_wt1l);
    cudaGetSymbolAddress((void**)&wt2h, g_wt2h); cudaGetSymbolAddress((void**)&wt2l, g_wt2l);
    cudaGetSymbolAddress((void**)&wf0h, g_wf0h); cudaGetSymbolAddress((void**)&wf0l, g_wf0l);
    cudaGetSymbolAddress((void**)&wf1h, g_wf1h); cudaGetSymbolAddress((void**)&wf1l, g_wf1l);
    cudaGetSymbolAddress((void**)&wf2h, g_wf2h); cudaGetSymbolAddress((void**)&wf2l, g_wf2l);

    // ---- graph normalization + CSR build ----
    k_detect<<<1, 1>>>((const long long*)ei);
    k_init_nodes<<<(NN + 255) / 256, 256>>>();
    k_edge_accum<<<(EE + 255) / 256, 256>>>(ei, ew);
    k_dis<<<(NN + 255) / 256, 256>>>();
    k_scan<<<1, 1024>>>();
    k_fill<<<(EE + 255) / 256, 256>>>(ew);

    // ---- weight transpose + bf16 split ----
    dim3 wtb(32, 8);
    k_wt<<<dim3(64 / 32, HID / 32), wtb>>>(W1, wt1h, wt1l, FEA, 64, HID);
    k_wt<<<dim3(HID / 32, HID / 32), wtb>>>(W2, wt2h, wt2l, HID, HID, HID);
    k_wt<<<dim3(FLATKP / 32, HID / 32), wtb>>>(Wf0, wf0h, wf0l, FLATK, FLATKP, HID);
    k_wt<<<dim3(HID / 32, HID / 32), wtb>>>(Wf1, wf1h, wf1l, HID, HID, HID);
    k_wt<<<dim3(HID / 32, HID / 32), wtb>>>(Wf2, wf2h, wf2l, HID, HID, HID);

    // ---- conv1: aggregate(x) -> tensor GEMM (K=64) ----
    k_gather_fea<<<NN, 64>>>(x);
    tgemm<0><<<dim3(HID / BN, NN / BM, 1), 256, SMEM_T>>>(
        axh, axl, wt1h, wt1l, b1, h1, nullptr, nullptr, HID, 64, 1 << 20);

    // ---- conv2: aggregate(h1) -> tensor GEMM (K=512) ----
    k_gather_hid<<<NN, 128>>>(h1);
    tgemm<0><<<dim3(HID / BN, NN / BM, 1), 256, SMEM_T>>>(
        ahh, ahl, wt2h, wt2l, b2, h1, nullptr, nullptr, HID, HID, 1 << 20);

    // ---- concat [h2, x] -> padded split [1024][12608] ----
    k_concat<<<(BATCH * FLATKP + 255) / 256, 256>>>(x, h1);

    // ---- MLP0: split-K x8 atomic (K=12608), then lrelu+split ----
    k_init_bias<<<(BATCH * HID + 255) / 256, 256>>>(m0, bf0, HID, BATCH * HID);
    tgemm<1><<<dim3(HID / BN, BATCH / BM, 8), 256, SMEM_T>>>(
        cth, ctl, wf0h, wf0l, nullptr, m0, nullptr, nullptr, HID, FLATKP, 50);
    k_lrelu_split<<<(BATCH * HID + 255) / 256, 256>>>(m0, m0h, m0l, BATCH * HID);

    // ---- MLP1: bias+lrelu -> bf16 split ----
    tgemm<2><<<dim3(HID / BN, BATCH / BM, 1), 256, SMEM_T>>>(
        m0h, m0l, wf1h, wf1l, bf1, nullptr, m1h, m1l, HID, HID, 1 << 20);

    // ---- MLP2: bias+lrelu -> fp32 ----
    tgemm<0><<<dim3(HID / BN, BATCH / BM, 1), 256, SMEM_T>>>(
        m1h, m1l, wf2h, wf2l, bf2, m2, nullptr, nullptr, HID, HID, 1 << 20);

    // ---- output head + log_softmax ----
    k_logits<<<BATCH, 128>>>(m2, Wo, bo, out);
}

// round 17
// speedup vs baseline: 1.9411x; 1.0480x over previous
#include <cuda_runtime.h>
#include <cuda_bf16.h>
#include <cstdint>

#define NN 22528
#define EE 360448
#define FEA 60
#define HID 512
#define BATCH 1024
#define CATW 572          // HID + FEA
#define FLATK 12584       // 22 * CATW
#define FLATKP 12608      // padded to %32
#define OUTC 4
#define SLOPE 0.01f

// ---- mma.sync GEMM tile config ----
#define BM 128
#define BN 128
#define BK 32
#define ASTRIDE 80        // smem row stride bytes (32 bf16 = 64B data + 16B pad)
#define SM_AH 0
#define SM_AL 10240
#define SM_BH 20480
#define SM_BL 30720
#define STAGE_BYTES 40960
#define SMEM_T (2 * STAGE_BYTES)   // 81920

// ---------------- scratch (device globals; no allocation allowed) -------------
__device__ int   g_is64;
__device__ float g_deg[NN];
__device__ float g_dis[NN];
__device__ int   g_cnt[NN];
__device__ int   g_off[NN + 1];
__device__ int   g_cur[NN];
__device__ int   g_row[EE];
__device__ int   g_col[EE];
__device__ int   g_srow[EE];
__device__ float g_snorm[EE];
__device__ float g_h1[(size_t)NN * HID];          // conv1 out only
__device__ float g_m0[BATCH * HID];
__device__ float g_m2[BATCH * HID];
// bf16 hi/lo activations
__device__ __nv_bfloat16 g_axh[(size_t)NN * 64],  g_axl[(size_t)NN * 64];
__device__ __nv_bfloat16 g_ahh[(size_t)NN * HID], g_ahl[(size_t)NN * HID];
__device__ __nv_bfloat16 g_cth[(size_t)BATCH * FLATKP], g_ctl[(size_t)BATCH * FLATKP];
__device__ __nv_bfloat16 g_m0h[BATCH * HID], g_m0l[BATCH * HID];
__device__ __nv_bfloat16 g_m1h[BATCH * HID], g_m1l[BATCH * HID];
// transposed + split weights: [Nn][KP] row-major
__device__ __nv_bfloat16 g_wt1h[(size_t)HID * 64],     g_wt1l[(size_t)HID * 64];
__device__ __nv_bfloat16 g_wt2h[(size_t)HID * HID],    g_wt2l[(size_t)HID * HID];
__device__ __nv_bfloat16 g_wf0h[(size_t)HID * FLATKP], g_wf0l[(size_t)HID * FLATKP];
__device__ __nv_bfloat16 g_wf1h[(size_t)HID * HID],    g_wf1l[(size_t)HID * HID];
__device__ __nv_bfloat16 g_wf2h[(size_t)HID * HID],    g_wf2l[(size_t)HID * HID];

// ---------------- helpers ------------------------------------------------------
__device__ __forceinline__ void split2(float v, __nv_bfloat16& h, __nv_bfloat16& l) {
    h = __float2bfloat16(v);
    l = __float2bfloat16(v - __bfloat162float(h));
}
__device__ __forceinline__ uint32_t smem_u32(const void* p) {
    uint32_t a;
    asm("{ .reg .u64 t; cvta.to.shared.u64 t, %1; cvt.u32.u64 %0, t; }" : "=r"(a) : "l"(p));
    return a;
}
__device__ __forceinline__ void cpa16(uint32_t dst, const void* src) {
    asm volatile("cp.async.cg.shared.global [%0], [%1], 16;" :: "r"(dst), "l"(src));
}
__device__ __forceinline__ void ldmx4(uint32_t* r, uint32_t addr) {
    asm volatile("ldmatrix.sync.aligned.m8n8.x4.shared.b16 {%0,%1,%2,%3}, [%4];"
        : "=r"(r[0]), "=r"(r[1]), "=r"(r[2]), "=r"(r[3]) : "r"(addr));
}
__device__ __forceinline__ void ldmx2(uint32_t* r, uint32_t addr) {
    asm volatile("ldmatrix.sync.aligned.m8n8.x2.shared.b16 {%0,%1}, [%2];"
        : "=r"(r[0]), "=r"(r[1]) : "r"(addr));
}
__device__ __forceinline__ void mma16816(float* c, const uint32_t* a, const uint32_t* b) {
    asm volatile("mma.sync.aligned.m16n8k16.row.col.f32.bf16.bf16.f32 "
        "{%0,%1,%2,%3}, {%4,%5,%6,%7}, {%8,%9}, {%0,%1,%2,%3};"
        : "+f"(c[0]), "+f"(c[1]), "+f"(c[2]), "+f"(c[3])
        : "r"(a[0]), "r"(a[1]), "r"(a[2]), "r"(a[3]), "r"(b[0]), "r"(b[1]));
}

// ---------------- edge-index dtype detection ---------------------------------
__global__ void k_detect(const long long* ei) {
    int bad = 0;
    for (int i = 0; i < 256; i++) {
        long long v = ei[i];
        if (v < 0 || v >= NN) bad = 1;
    }
    g_is64 = bad ? 0 : 1;
}

__global__ void k_init_nodes() {
    int i = blockIdx.x * blockDim.x + threadIdx.x;
    if (i < NN) { g_deg[i] = 1.0f; g_cnt[i] = 0; }
}

__global__ void k_edge_accum(const void* ei, const float* __restrict__ ew) {
    int e = blockIdx.x * blockDim.x + threadIdx.x;
    if (e >= EE) return;
    int r, c;
    if (g_is64) {
        const long long* p = (const long long*)ei;
        r = (int)p[e]; c = (int)p[EE + e];
    } else {
        const int* p = (const int*)ei;
        r = p[e]; c = p[EE + e];
    }
    g_row[e] = r; g_col[e] = c;
    atomicAdd(&g_deg[c], ew[e]);
    atomicAdd(&g_cnt[c], 1);
}

__global__ void k_dis() {
    int i = blockIdx.x * blockDim.x + threadIdx.x;
    if (i < NN) g_dis[i] = rsqrtf(g_deg[i]);
}

__global__ void k_scan() {
    __shared__ int sums[1024];
    const int CH = NN / 1024;   // 22
    int t = threadIdx.x;
    int base = t * CH;
    int loc[CH];
    int s = 0;
#pragma unroll
    for (int i = 0; i < CH; i++) { loc[i] = s; s += g_cnt[base + i]; }
    sums[t] = s;
    __syncthreads();
    for (int d = 1; d < 1024; d <<= 1) {
        int v = 0;
        if (t >= d) v = sums[t - d];
        __syncthreads();
        if (t >= d) sums[t] += v;
        __syncthreads();
    }
    int off = (t == 0) ? 0 : sums[t - 1];
#pragma unroll
    for (int i = 0; i < CH; i++) {
        int o = off + loc[i];
        g_off[base + i] = o;
        g_cur[base + i] = o;
    }
    if (t == 1023) g_off[NN] = sums[1023];
}

__global__ void k_fill(const float* __restrict__ ew) {
    int e = blockIdx.x * blockDim.x + threadIdx.x;
    if (e >= EE) return;
    int r = g_row[e], c = g_col[e];
    int p = atomicAdd(&g_cur[c], 1);
    g_srow[p] = r;
    g_snorm[p] = g_dis[r] * ew[e] * g_dis[c];
}

// ---------------- graph aggregation (gather, CSR) → bf16 split ----------------
__global__ void k_gather_fea(const float* __restrict__ x) {
    int n = blockIdx.x;
    int t = threadIdx.x;   // 64
    __shared__ int   sr[64];
    __shared__ float sw[64];
    int beg = g_off[n], end = g_off[n + 1];
    float dn = g_dis[n];
    float self = dn * dn;
    float acc = 0.f;
    if (t < FEA) acc = x[(size_t)n * FEA + t] * self;
    for (int ch = beg; ch < end; ch += 64) {
        int m = min(64, end - ch);
        if (t < m) { sr[t] = g_srow[ch + t]; sw[t] = g_snorm[ch + t]; }
        __syncthreads();
        if (t < FEA) {
            for (int k = 0; k < m; k++)
                acc = fmaf(x[(size_t)sr[k] * FEA + t], sw[k], acc);
        }
        __syncthreads();
    }
    float v = (t < FEA) ? acc : 0.f;
    __nv_bfloat16 h, l;
    split2(v, h, l);
    g_axh[(size_t)n * 64 + t] = h;
    g_axl[(size_t)n * 64 + t] = l;
}

__global__ void k_gather_hid(const float* __restrict__ in) {
    int n = blockIdx.x;
    int t = threadIdx.x;   // 128
    __shared__ int   sr[64];
    __shared__ float sw[64];
    int beg = g_off[n], end = g_off[n + 1];
    float dn = g_dis[n];
    float self = dn * dn;
    float4 acc = *(const float4*)(in + (size_t)n * HID + t * 4);
    acc.x *= self; acc.y *= self; acc.z *= self; acc.w *= self;
    for (int ch = beg; ch < end; ch += 64) {
        int m = min(64, end - ch);
        if (t < m) { sr[t] = g_srow[ch + t]; sw[t] = g_snorm[ch + t]; }
        __syncthreads();
        for (int k = 0; k < m; k++) {
            float4 u = *(const float4*)(in + (size_t)sr[k] * HID + t * 4);
            float w = sw[k];
            acc.x = fmaf(u.x, w, acc.x);
            acc.y = fmaf(u.y, w, acc.y);
            acc.z = fmaf(u.z, w, acc.z);
            acc.w = fmaf(u.w, w, acc.w);
        }
        __syncthreads();
    }
    __nv_bfloat16 h0, l0, h1, l1, h2, l2, h3, l3;
    split2(acc.x, h0, l0); split2(acc.y, h1, l1);
    split2(acc.z, h2, l2); split2(acc.w, h3, l3);
    size_t o = (size_t)n * HID + t * 4;
    g_ahh[o + 0] = h0; g_ahh[o + 1] = h1; g_ahh[o + 2] = h2; g_ahh[o + 3] = h3;
    g_ahl[o + 0] = l0; g_ahl[o + 1] = l1; g_ahl[o + 2] = l2; g_ahl[o + 3] = l3;
}

// ---------------- weight transpose + split: W[K][Nn] -> Wh/Wl[Nn][KP] ---------
__global__ void k_wt(const float* __restrict__ W, __nv_bfloat16* __restrict__ Wh,
                     __nv_bfloat16* __restrict__ Wl, int K, int KP, int Nn) {
    __shared__ float sm[32][33];
    int k0 = blockIdx.x * 32, n0 = blockIdx.y * 32;
    int tx = threadIdx.x, ty = threadIdx.y;   // (32, 8)
    for (int i = ty; i < 32; i += 8) {
        int k = k0 + i;
        sm[i][tx] = (k < K) ? W[(size_t)k * Nn + n0 + tx] : 0.f;
    }
    __syncthreads();
    for (int i = ty; i < 32; i += 8) {
        int n = n0 + i, k = k0 + tx;
        float v = sm[tx][i];
        __nv_bfloat16 h, l;
        split2(v, h, l);
        Wh[(size_t)n * KP + k] = h;
        Wl[(size_t)n * KP + k] = l;
    }
}

// ---------------- bf16 mma.sync GEMM -------------------------------------------
// C[M,Nn] = A @ B^T. 3-term split, fp32 accum. BM=128, BN=128, 8 warps (4x2),
// warp tile 32x64. EPI: 0=bias+lrelu->f32, 1=atomicAdd->f32,
// 2=bias+lrelu->bf16 pair, 3=bias+lrelu->bf16 pair at concat-reshaped address.
template <int EPI>
__global__ __launch_bounds__(256) void tgemm(
    const __nv_bfloat16* __restrict__ Ah, const __nv_bfloat16* __restrict__ Al,
    const __nv_bfloat16* __restrict__ Bh, const __nv_bfloat16* __restrict__ Bl,
    const float* __restrict__ bias, float* __restrict__ C,
    __nv_bfloat16* __restrict__ Ch, __nv_bfloat16* __restrict__ Cl,
    int Nn, int K, int chunksPerSlab)
{
    extern __shared__ char smem[];
    uint32_t sbase = smem_u32(smem);
    int tid = threadIdx.x, lane = tid & 31, w = tid >> 5;
    int wm = w & 3, wn = w >> 2;              // 4 x 2 warps, warp tile 32x64
    int rowBase = blockIdx.y * BM, colBase = blockIdx.x * BN;
    int total = K / BK;
    int c0 = blockIdx.z * chunksPerSlab;
    int c1 = min(total, c0 + chunksPerSlab);

    float acc[2][8][4];
#pragma unroll
    for (int i = 0; i < 2; i++)
#pragma unroll
        for (int j = 0; j < 8; j++)
#pragma unroll
            for (int q = 0; q < 4; q++) acc[i][j][q] = 0.f;

#define LOADSTAGE(chunk, stg) do {                                             \
        int kk = (chunk) * BK;                                                 \
        uint32_t sb = sbase + (stg) * STAGE_BYTES;                             \
        _Pragma("unroll")                                                      \
        for (int i_ = 0; i_ < 2; i_++) {                                       \
            int t2 = tid + i_ * 256; int r_ = t2 >> 2, c_ = t2 & 3;            \
            size_t soA = (size_t)(rowBase + r_) * K + kk + c_ * 8;             \
            size_t soB = (size_t)(colBase + r_) * K + kk + c_ * 8;             \
            uint32_t d_ = sb + r_ * ASTRIDE + c_ * 16;                         \
            cpa16(d_ + SM_AH, Ah + soA);                                       \
            cpa16(d_ + SM_AL, Al + soA);                                       \
            cpa16(d_ + SM_BH, Bh + soB);                                       \
            cpa16(d_ + SM_BL, Bl + soB);                                       \
        }                                                                      \
        asm volatile("cp.async.commit_group;" ::: "memory");                   \
    } while (0)

    LOADSTAGE(c0, 0);
    for (int c = c0; c < c1; ++c) {
        int stg = (c - c0) & 1;
        if (c + 1 < c1) {
            LOADSTAGE(c + 1, stg ^ 1);
            asm volatile("cp.async.wait_group 1;" ::: "memory");
        } else {
            asm volatile("cp.async.wait_group 0;" ::: "memory");
        }
        __syncthreads();
        uint32_t sb = sbase + stg * STAGE_BYTES;
        uint32_t aB = sb + SM_AH + wm * 32 * ASTRIDE;
        uint32_t bB = sb + SM_BH + wn * 64 * ASTRIDE;
        int lr = lane & 15, lh = lane >> 4;
        int bn = lane & 7, bk = (lane >> 3) & 1;
#pragma unroll
        for (int ks = 0; ks < 2; ks++) {
            int ko = ks * 32;   // bytes (16 bf16)
            uint32_t ah[2][4], al[2][4], bh[8][2], bl[8][2];
#pragma unroll
            for (int mi = 0; mi < 2; mi++) {
                uint32_t ad = aB + (mi * 16 + lr) * ASTRIDE + ko + lh * 16;
                ldmx4(ah[mi], ad);
                ldmx4(al[mi], ad + (SM_AL - SM_AH));
            }
#pragma unroll
            for (int ni = 0; ni < 8; ni++) {
                uint32_t bd = bB + (ni * 8 + bn) * ASTRIDE + ko + bk * 16;
                ldmx2(bh[ni], bd);
                ldmx2(bl[ni], bd + (SM_BL - SM_BH));
            }
#pragma unroll
            for (int mi = 0; mi < 2; mi++)
#pragma unroll
                for (int ni = 0; ni < 8; ni++) {
                    mma16816(acc[mi][ni], ah[mi], bh[ni]);
                    mma16816(acc[mi][ni], al[mi], bh[ni]);
                    mma16816(acc[mi][ni], ah[mi], bl[ni]);
                }
        }
        __syncthreads();
    }
#undef LOADSTAGE

    // epilogue
    int r0 = rowBase + wm * 32 + (lane >> 2);
    int cB = colBase + wn * 64 + 2 * (lane & 3);
#pragma unroll
    for (int mi = 0; mi < 2; mi++)
#pragma unroll
        for (int ni = 0; ni < 8; ni++) {
            int row = r0 + mi * 16, col = cB + ni * 8;
            float* a = acc[mi][ni];
            if (EPI == 1) {
                atomicAdd(&C[(size_t)row * Nn + col],           a[0]);
                atomicAdd(&C[(size_t)row * Nn + col + 1],       a[1]);
                atomicAdd(&C[(size_t)(row + 8) * Nn + col],     a[2]);
                atomicAdd(&C[(size_t)(row + 8) * Nn + col + 1], a[3]);
            } else {
                float b0 = bias[col], b1 = bias[col + 1];
                float v0 = a[0] + b0, v1 = a[1] + b1;
                float v2 = a[2] + b0, v3 = a[3] + b1;
                v0 = v0 > 0.f ? v0 : SLOPE * v0;
                v1 = v1 > 0.f ? v1 : SLOPE * v1;
                v2 = v2 > 0.f ? v2 : SLOPE * v2;
                v3 = v3 > 0.f ? v3 : SLOPE * v3;
                if (EPI == 0) {
                    *(float2*)&C[(size_t)row * Nn + col]       = make_float2(v0, v1);
                    *(float2*)&C[(size_t)(row + 8) * Nn + col] = make_float2(v2, v3);
                } else {
                    __nv_bfloat16 h0, l0, h1, l1, h2, l2, h3, l3;
                    split2(v0, h0, l0); split2(v1, h1, l1);
                    split2(v2, h2, l2); split2(v3, h3, l3);
                    __nv_bfloat162 H0; H0.x = h0; H0.y = h1;
                    __nv_bfloat162 L0; L0.x = l0; L0.y = l1;
                    __nv_bfloat162 H1; H1.x = h2; H1.y = h3;
                    __nv_bfloat162 L1; L1.x = l2; L1.y = l3;
                    if (EPI == 2) {
                        *(__nv_bfloat162*)&Ch[(size_t)row * Nn + col]       = H0;
                        *(__nv_bfloat162*)&Cl[(size_t)row * Nn + col]       = L0;
                        *(__nv_bfloat162*)&Ch[(size_t)(row + 8) * Nn + col] = H1;
                        *(__nv_bfloat162*)&Cl[(size_t)(row + 8) * Nn + col] = L1;
                    } else {  // EPI == 3: concat-reshaped address
                        int ba = row / 22, nl = row - ba * 22;
                        size_t ad0 = (size_t)ba * FLATKP + nl * CATW + col;
                        int rb = row + 8;
                        int bb_ = rb / 22, nlb = rb - bb_ * 22;
                        size_t ad1 = (size_t)bb_ * FLATKP + nlb * CATW + col;
                        *(__nv_bfloat162*)&Ch[ad0] = H0;
                        *(__nv_bfloat162*)&Cl[ad0] = L0;
                        *(__nv_bfloat162*)&Ch[ad1] = H1;
                        *(__nv_bfloat162*)&Cl[ad1] = L1;
                    }
                }
            }
        }
}

// ---------------- misc elementwise --------------------------------------------
// Fill x-columns [512,572) of the concat buffer + zero padding [12584,12608)
__global__ void k_catx(const float* __restrict__ x) {
    const int PER_B = 22 * FEA + (FLATKP - FLATK);   // 1320 + 24 = 1344
    int i = blockIdx.x * blockDim.x + threadIdx.x;
    if (i >= BATCH * PER_B) return;
    int b = i / PER_B;
    int sub = i - b * PER_B;
    float v = 0.f;
    size_t addr;
    if (sub < 22 * FEA) {
        int nl = sub / FEA, c = sub - nl * FEA;
        v = x[(size_t)(b * 22 + nl) * FEA + c];
        addr = (size_t)b * FLATKP + nl * CATW + HID + c;
    } else {
        addr = (size_t)b * FLATKP + FLATK + (sub - 22 * FEA);
    }
    __nv_bfloat16 h, l;
    split2(v, h, l);
    g_cth[addr] = h; g_ctl[addr] = l;
}

__global__ void k_init_bias(float* __restrict__ C, const float* __restrict__ b, int Nn, int total) {
    int i = blockIdx.x * blockDim.x + threadIdx.x;
    if (i < total) C[i] = b[i % Nn];
}

__global__ void k_lrelu_split(const float* __restrict__ m,
                              __nv_bfloat16* __restrict__ mh, __nv_bfloat16* __restrict__ ml,
                              int total) {
    int i = blockIdx.x * blockDim.x + threadIdx.x;
    if (i >= total) return;
    float v = m[i];
    v = v > 0.f ? v : SLOPE * v;
    __nv_bfloat16 h, l;
    split2(v, h, l);
    mh[i] = h; ml[i] = l;
}

// ---------------- final layer + log_softmax -----------------------------------
__global__ void k_logits(const float* __restrict__ m2, const float* __restrict__ Wo,
                         const float* __restrict__ bo, float* __restrict__ out) {
    int b = blockIdx.x;
    int t = threadIdx.x;
    int w = t >> 5, lane = t & 31;
    float s = 0.f;
    const float* mr = m2 + (size_t)b * HID;
    for (int k = lane; k < HID; k += 32)
        s = fmaf(mr[k], Wo[k * OUTC + w], s);
#pragma unroll
    for (int o = 16; o; o >>= 1) s += __shfl_xor_sync(0xffffffffu, s, o);
    __shared__ float lg[OUTC];
    if (lane == 0) lg[w] = s + bo[w];
    __syncthreads();
    if (t == 0) {
        float a = lg[0], bb = lg[1], c = lg[2], d = lg[3];
        float mx = fmaxf(fmaxf(a, bb), fmaxf(c, d));
        float se = expf(a - mx) + expf(bb - mx) + expf(c - mx) + expf(d - mx);
        float l = mx + logf(se);
        out[b * OUTC + 0] = a - l;
        out[b * OUTC + 1] = bb - l;
        out[b * OUTC + 2] = c - l;
        out[b * OUTC + 3] = d - l;
    }
}

// ---------------- launch -------------------------------------------------------
extern "C" void kernel_launch(void* const* d_in, const int* in_sizes, int n_in,
                              void* d_out, int out_size) {
    const float* x   = (const float*)d_in[0];
    const void*  ei  = d_in[1];
    const float* ew  = (const float*)d_in[2];
    const float* W1  = (const float*)d_in[3];
    const float* b1  = (const float*)d_in[4];
    const float* W2  = (const float*)d_in[5];
    const float* b2  = (const float*)d_in[6];
    const float* Wf0 = (const float*)d_in[7];
    const float* bf0 = (const float*)d_in[8];
    const float* Wf1 = (const float*)d_in[9];
    const float* bf1 = (const float*)d_in[10];
    const float* Wf2 = (const float*)d_in[11];
    const float* bf2 = (const float*)d_in[12];
    const float* Wo  = (const float*)d_in[13];
    const float* bo  = (const float*)d_in[14];
    float* out = (float*)d_out;

    cudaFuncSetAttribute(tgemm<0>, cudaFuncAttributeMaxDynamicSharedMemorySize, SMEM_T);
    cudaFuncSetAttribute(tgemm<1>, cudaFuncAttributeMaxDynamicSharedMemorySize, SMEM_T);
    cudaFuncSetAttribute(tgemm<2>, cudaFuncAttributeMaxDynamicSharedMemorySize, SMEM_T);
    cudaFuncSetAttribute(tgemm<3>, cudaFuncAttributeMaxDynamicSharedMemorySize, SMEM_T);

    float *h1, *m0, *m2;
    __nv_bfloat16 *axh, *axl, *ahh, *ahl, *cth, *ctl, *m0h, *m0l, *m1h, *m1l;
    __nv_bfloat16 *wt1h, *wt1l, *wt2h, *wt2l, *wf0h, *wf0l, *wf1h, *wf1l, *wf2h, *wf2l;
    cudaGetSymbolAddress((void**)&h1,  g_h1);
    cudaGetSymbolAddress((void**)&m0,  g_m0);
    cudaGetSymbolAddress((void**)&m2,  g_m2);
    cudaGetSymbolAddress((void**)&axh, g_axh);  cudaGetSymbolAddress((void**)&axl, g_axl);
    cudaGetSymbolAddress((void**)&ahh, g_ahh);  cudaGetSymbolAddress((void**)&ahl, g_ahl);
    cudaGetSymbolAddress((void**)&cth, g_cth);  cudaGetSymbolAddress((void**)&ctl, g_ctl);
    cudaGetSymbolAddress((void**)&m0h, g_m0h);  cudaGetSymbolAddress((void**)&m0l, g_m0l);
    cudaGetSymbolAddress((void**)&m1h, g_m1h);  cudaGetSymbolAddress((void**)&m1l, g_m1l);
    cudaGetSymbolAddress((void**)&wt1h, g_wt1h); cudaGetSymbolAddress((void**)&wt1l, g_wt1l);
    cudaGetSymbolAddress((void**)&wt2h, g_wt2h); cudaGetSymbolAddress((void**)&wt2l, g_wt2l);
    cudaGetSymbolAddress((void**)&wf0h, g_wf0h); cudaGetSymbolAddress((void**)&wf0l, g_wf0l);
    cudaGetSymbolAddress((void**)&wf1h, g_wf1h); cudaGetSymbolAddress((void**)&wf1l, g_wf1l);
    cudaGetSymbolAddress((void**)&wf2h, g_wf2h); cudaGetSymbolAddress((void**)&wf2l, g_wf2l);

    // ---- graph normalization + CSR build ----
    k_detect<<<1, 1>>>((const long long*)ei);
    k_init_nodes<<<(NN + 255) / 256, 256>>>();
    k_edge_accum<<<(EE + 255) / 256, 256>>>(ei, ew);
    k_dis<<<(NN + 255) / 256, 256>>>();
    k_scan<<<1, 1024>>>();
    k_fill<<<(EE + 255) / 256, 256>>>(ew);

    // ---- weight transpose + bf16 split ----
    dim3 wtb(32, 8);
    k_wt<<<dim3(64 / 32, HID / 32), wtb>>>(W1, wt1h, wt1l, FEA, 64, HID);
    k_wt<<<dim3(HID / 32, HID / 32), wtb>>>(W2, wt2h, wt2l, HID, HID, HID);
    k_wt<<<dim3(FLATKP / 32, HID / 32), wtb>>>(Wf0, wf0h, wf0l, FLATK, FLATKP, HID);
    k_wt<<<dim3(HID / 32, HID / 32), wtb>>>(Wf1, wf1h, wf1l, HID, HID, HID);
    k_wt<<<dim3(HID / 32, HID / 32), wtb>>>(Wf2, wf2h, wf2l, HID, HID, HID);

    // ---- conv1: aggregate(x) -> tensor GEMM (K=64) -> h1 fp32 ----
    k_gather_fea<<<NN, 64>>>(x);
    tgemm<0><<<dim3(HID / BN, NN / BM, 1), 256, SMEM_T>>>(
        axh, axl, wt1h, wt1l, b1, h1, nullptr, nullptr, HID, 64, 1 << 20);

    // ---- conv2: aggregate(h1) -> tensor GEMM, epilogue writes concat split ----
    k_gather_hid<<<NN, 128>>>(h1);
    k_catx<<<(BATCH * 1344 + 255) / 256, 256>>>(x);
    tgemm<3><<<dim3(HID / BN, NN / BM, 1), 256, SMEM_T>>>(
        ahh, ahl, wt2h, wt2l, b2, nullptr, cth, ctl, HID, HID, 1 << 20);

    // ---- MLP0: split-K x8 atomic (K=12608), then lrelu+split ----
    k_init_bias<<<(BATCH * HID + 255) / 256, 256>>>(m0, bf0, HID, BATCH * HID);
    tgemm<1><<<dim3(HID / BN, BATCH / BM, 8), 256, SMEM_T>>>(
        cth, ctl, wf0h, wf0l, nullptr, m0, nullptr, nullptr, HID, FLATKP, 50);
    k_lrelu_split<<<(BATCH * HID + 255) / 256, 256>>>(m0, m0h, m0l, BATCH * HID);

    // ---- MLP1: bias+lrelu -> bf16 split ----
    tgemm<2><<<dim3(HID / BN, BATCH / BM, 1), 256, SMEM_T>>>(
        m0h, m0l, wf1h, wf1l, bf1, nullptr, m1h, m1l, HID, HID, 1 << 20);

    // ---- MLP2: bias+lrelu -> fp32 ----
    tgemm<0><<<dim3(HID / BN, BATCH / BM, 1), 256, SMEM_T>>>(
        m1h, m1l, wf2h, wf2l, bf2, m2, nullptr, nullptr, HID, HID, 1 << 20);

    // ---- output head + log_softmax ----
    k_logits<<<BATCH, 128>>>(m2, Wo, bo, out);
}